// round 13
// baseline (speedup 1.0000x reference)
#include <cuda_runtime.h>
#include <math.h>

#define TGT 20
#define BATCH 64
#define BLOCK 1024
#define NWARP (BLOCK / 32)
#define MAXA 9408
#define NBLK (3 * BATCH)
#define SEG 128                       // per-warp compaction segment (power of 2)

// dynamic smem layout (bytes)
#define OFF_VAL  0            // u32/f32[MAXA] 37632: iou bits -> bce (neg sign-enc)
#define OFF_HIST 37632        // u32[2048]  8192
#define OFF_LIST 45824        // f32[NWARP*SEG] 16384
#define SMEM_BYTES 62208

#define MARK 0x7F800001u      // forced-override marker base (NaN space)
#define IOU03 0x3E99999Au     // bits of 0.3f
#define IOU05 0x3F000000u     // bits of 0.5f

struct Sh {
    float tb[TGT][4];
    float tarea[TGT];
    int   tlab[TGT];
    int   rc0[TGT], rr0[TGT], rw[TGT];
    int   cum[TGT + 1];
    unsigned long long best[TGT];
    float wred[NWARP][8];
    float out[8];
    unsigned warpTot[NWARP];
    unsigned warpSE[NWARP];
    unsigned wcnt[NWARP];
    int selBucket;
    unsigned selAbove;
    int overflow;
    int isLast;
};

__device__ float g_partials[NBLK * 3];
__device__ unsigned g_done = 0;

template<int N>
__device__ __forceinline__ void redN(float* v, Sh& sh) {
    int lane = threadIdx.x & 31, wid = threadIdx.x >> 5;
    #pragma unroll
    for (int i = 0; i < N; i++) {
        float x = v[i];
        #pragma unroll
        for (int off = 16; off; off >>= 1) x += __shfl_xor_sync(0xffffffffu, x, off);
        if (lane == 0) sh.wred[wid][i] = x;
    }
    __syncthreads();
    if (threadIdx.x < N) {
        float s = 0.f;
        #pragma unroll
        for (int w = 0; w < NWARP; w++) s += sh.wred[w][threadIdx.x];
        sh.out[threadIdx.x] = s;
    }
    __syncthreads();
}

template<int NB>
__device__ void selectBucket(unsigned* hist, int kRem, Sh& sh) {
    const int tid = threadIdx.x;
    constexpr int CH = (NB >= BLOCK) ? NB / BLOCK : 1;
    int basei = tid * CH;
    unsigned ls = 0;
    if (basei < NB)
        #pragma unroll
        for (int j = 0; j < CH; j++) ls += hist[basei + j];
    int lane = tid & 31, wid = tid >> 5;
    unsigned v = ls;
    #pragma unroll
    for (int off = 1; off < 32; off <<= 1) {
        unsigned w2 = __shfl_down_sync(0xffffffffu, v, off);
        if (lane + off < 32) v += w2;
    }
    if (lane == 0) sh.warpTot[wid] = v;
    __syncthreads();
    if (tid < NWARP) {
        unsigned wv = sh.warpTot[tid];
        unsigned ws = wv;
        #pragma unroll
        for (int off = 1; off < NWARP; off <<= 1) {
            unsigned w2 = __shfl_down_sync(0xffffffffu, ws, off);
            if (tid + off < NWARP) ws += w2;
        }
        sh.warpSE[tid] = ws - wv;
    }
    __syncthreads();
    unsigned SE = sh.warpSE[wid] + (v - ls);
    if (basei < NB && SE < (unsigned)kRem && SE + ls >= (unsigned)kRem) {
        unsigned c = SE;
        #pragma unroll
        for (int j = CH - 1; j >= 0; j--) {
            unsigned hv = hist[basei + j];
            if (c + hv >= (unsigned)kRem) { sh.selBucket = basei + j; sh.selAbove = c; break; }
            c += hv;
        }
    }
    __syncthreads();
}

template<int F>
__device__ void run_scale(const float* __restrict__ pred,
                          const float* __restrict__ tb,
                          const int* __restrict__ tl,
                          float* __restrict__ out,
                          int b, int scale,
                          unsigned char* dyn, Sh& sh)
{
    constexpr int FSQ = F * F;
    constexpr int A = FSQ * 3;
    constexpr float STRIDE = 448.0f / (float)F;
    constexpr float INV = (float)F / 448.0f;   // exact (1/8, 1/16, 1/32)

    unsigned* s_iou = (unsigned*)(dyn + OFF_VAL);
    float* s_bce = (float*)(dyn + OFF_VAL);      // aliased: iou consumed -> bce stored
    unsigned* hist = (unsigned*)(dyn + OFF_HIST);
    float* list = (float*)(dyn + OFF_LIST);

    const int tid = threadIdx.x;
    const int lane = tid & 31;
    const int wid = tid >> 5;

    if (tid < TGT) {
        const float* p = tb + (size_t)(b * TGT + tid) * 4;
        float x1 = p[0], y1 = p[1], x2 = p[2], y2 = p[3];
        sh.tb[tid][0] = x1; sh.tb[tid][1] = y1; sh.tb[tid][2] = x2; sh.tb[tid][3] = y2;
        sh.tarea[tid] = (x2 - x1) * (y2 - y1);
        sh.tlab[tid] = tl[b * TGT + tid];
        sh.best[tid] = 0ull;
        const float half3 = 1.5f * STRIDE;
        int c0 = max(0, (int)floorf((x1 - half3) * INV - 0.5f));
        int c1 = min(F - 1, (int)ceilf((x2 + half3) * INV - 0.5f));
        int r0 = max(0, (int)floorf((y1 - half3) * INV - 0.5f));
        int r1 = min(F - 1, (int)ceilf((y2 + half3) * INV - 0.5f));
        int w = c1 - c0 + 1, hh = r1 - r0 + 1;
        sh.rc0[tid] = c0; sh.rr0[tid] = r0;
        sh.rw[tid] = max(w, 1);
        sh.cum[tid] = (w > 0 && hh > 0) ? w * hh : 0;  // temp: size
    }
    {
        uint4 z4 = make_uint4(0u, 0u, 0u, 0u);
        uint4* p4 = (uint4*)s_iou;
        for (int i = tid; i < A / 4; i += BLOCK) p4[i] = z4;
    }
    for (int i = tid; i < 1024; i += BLOCK) hist[i] = 0;
    __syncthreads();
    if (tid == 0) {
        int s = 0;
        #pragma unroll
        for (int t = 0; t < TGT; t++) { int sz = sh.cum[t]; sh.cum[t] = s; s += sz; }
        sh.cum[TGT] = s;
    }
    __syncthreads();

    const float* predb = pred + (size_t)b * 24 * FSQ;

    // ---------- Phase 1: flattened (target,cell) scatter ----------
    {
        const int total = sh.cum[TGT];
        const int totalP = (total + BLOCK - 1) & ~(BLOCK - 1);
        int tcur = 0;
        for (int idx = tid; idx < totalP; idx += BLOCK) {
            bool valid = idx < total;
            int tt = -1;
            unsigned long long pk = 0ull;
            if (valid) {
                while (idx >= sh.cum[tcur + 1]) tcur++;
                tt = tcur;
                int local = idx - sh.cum[tt];
                int w = sh.rw[tt];
                int rr = local / w, cc = local - rr * w;
                int r = sh.rr0[tt] + rr, c = sh.rc0[tt] + cc;
                float cx = ((float)c + 0.5f) * STRIDE;
                float cy = ((float)r + 0.5f) * STRIDE;
                float tx1 = sh.tb[tt][0], ty1 = sh.tb[tt][1];
                float tx2 = sh.tb[tt][2], ty2 = sh.tb[tt][3];
                float ta = sh.tarea[tt];
                int abase = (r * F + c) * 3;
                // largest anchor (ai=2) first: anchors are concentric squares,
                // so an empty ai=2 intersection implies empty ai=0/1 too.
                const float h2 = 1.5f * STRIDE;
                float lx2 = fmaxf(cx - h2, tx1), ly2 = fmaxf(cy - h2, ty1);
                float rx2 = fminf(cx + h2, tx2), ry2 = fminf(cy + h2, ty2);
                float iw2 = rx2 - lx2, ih2 = ry2 - ly2;
                if (iw2 > 0.f && ih2 > 0.f) {
                    {   // ai = 2
                        float I = iw2 * ih2;
                        float U = (2.f * h2) * (2.f * h2) + ta - I;
                        unsigned ib = __float_as_uint(__fdividef(I, U + 1e-9f));
                        if (ib >= IOU03) atomicMax(&s_iou[abase + 2], ib);
                        unsigned long long cand = ((unsigned long long)ib << 32) |
                            (unsigned long long)(0xffffffffu - (unsigned)(abase + 2));
                        if (cand > pk) pk = cand;
                    }
                    #pragma unroll
                    for (int ai = 0; ai < 2; ai++) {
                        float half = (1.0f + 0.25f * (float)ai) * STRIDE;
                        float lx = fmaxf(cx - half, tx1), ly = fmaxf(cy - half, ty1);
                        float rx = fminf(cx + half, tx2), ry = fminf(cy + half, ty2);
                        float iw = rx - lx, ih = ry - ly;
                        if (iw > 0.f && ih > 0.f) {
                            float I = iw * ih;
                            float areaA = (2.f * half) * (2.f * half);
                            float U = areaA + ta - I;
                            unsigned ib = __float_as_uint(__fdividef(I, U + 1e-9f));
                            if (ib >= IOU03) atomicMax(&s_iou[abase + ai], ib);
                            unsigned long long cand = ((unsigned long long)ib << 32) |
                                (unsigned long long)(0xffffffffu - (unsigned)(abase + ai));
                            if (cand > pk) pk = cand;
                        }
                    }
                }
            }
            #pragma unroll
            for (int off = 1; off < 32; off <<= 1) {
                unsigned long long opk = __shfl_up_sync(0xffffffffu, pk, off);
                int ot = __shfl_up_sync(0xffffffffu, tt, off);
                if (lane >= off && ot == tt && opk > pk) pk = opk;
            }
            unsigned mask = __match_any_sync(0xffffffffu, tt);
            int hi = 31 - __clz(mask);
            if (tt >= 0 && lane == hi && pk)
                atomicMax(&sh.best[tt], pk);
        }
    }
    __syncthreads();

    // ---------- Phase 2: forced-positive override marker (last target wins) ----------
    if (tid == 0) {
        #pragma unroll
        for (int t = 0; t < TGT; t++) {
            if (sh.best[t]) {
                unsigned a = 0xffffffffu - (unsigned)(sh.best[t] & 0xffffffffull);
                s_iou[a] = MARK + (unsigned)t;
            }
        }
    }
    __syncthreads();

    // ---------- Phase 3: BCE + fused level-0 hist + positive losses ----------
    float acc[5] = {0.f, 0.f, 0.f, 0.f, 0.f}; // posBce, ce, sl, cntPos, cntNeg
    constexpr int FSQP = ((FSQ + BLOCK - 1) / BLOCK) * BLOCK;
    for (int cell = tid; cell < FSQP; cell += BLOCK) {
        bool act = cell < FSQ;
        int row = 0, col = 0;
        float cx = 0.f, cy = 0.f;
        if (act) {
            row = cell / F; col = cell - row * F;
            cx = ((float)col + 0.5f) * STRIDE;
            cy = ((float)row + 0.5f) * STRIDE;
        }
        #pragma unroll
        for (int ai = 0; ai < 3; ai++) {
            int a = cell * 3 + ai;
            unsigned ib = 0; float x = 0.f;
            if (act) { ib = s_iou[a]; x = predb[(ai * 8 + 4) * FSQ + cell]; }
            bool forced = ib >= MARK;
            bool pos = forced || (act && ib >= IOU05);
            bool neg = act && !forced && ib < IOU03;
            float bce = fmaxf(x, 0.f) - (pos ? x : 0.f) + __logf(1.f + __expf(-fabsf(x)));
            if (act) s_bce[a] = neg ? -bce : bce;
            int bin = neg ? (int)(__float_as_uint(bce) >> 21) : -1;
            unsigned mask = __match_any_sync(0xffffffffu, bin);
            if (bin >= 0) {
                acc[4] += 1.f;
                if (lane == __ffs(mask) - 1) atomicAdd(&hist[bin], (unsigned)__popc(mask));
            }
            if (pos) {
                acc[3] += 1.f; acc[0] += bce;
                int t = 0;
                if (forced) t = (int)(ib - MARK);
                else {
                    #pragma unroll
                    for (int q = 0; q < TGT; q++) {
                        float half = (1.0f + 0.25f * (float)ai) * STRIDE;
                        float lx = fmaxf(cx - half, sh.tb[q][0]);
                        float ly = fmaxf(cy - half, sh.tb[q][1]);
                        float rx = fminf(cx + half, sh.tb[q][2]);
                        float ry = fminf(cy + half, sh.tb[q][3]);
                        float iw = rx - lx, ih = ry - ly;
                        if (iw > 0.f && ih > 0.f) {
                            float I = iw * ih;
                            float areaA = (2.f * half) * (2.f * half);
                            float U = areaA + sh.tarea[q] - I;
                            if (__float_as_uint(__fdividef(I, U + 1e-9f)) == ib) { t = q; break; }
                        }
                    }
                }
                const float* pb = predb + cell;
                int cs = ai * 8;
                float c0v = pb[(cs + 5) * FSQ], c1v = pb[(cs + 6) * FSQ], c2v = pb[(cs + 7) * FSQ];
                float m = fmaxf(c0v, fmaxf(c1v, c2v));
                float lse = m + __logf(__expf(c0v - m) + __expf(c1v - m) + __expf(c2v - m));
                int tg = sh.tlab[t] - 1;
                float ct = (tg == 0) ? c0v : ((tg == 1) ? c1v : c2v);
                acc[1] += lse - ct;
                float half = (1.0f + 0.25f * (float)ai) * STRIDE;
                float aw = 2.f * half;
                float gx1 = sh.tb[t][0], gy1 = sh.tb[t][1];
                float gx2 = sh.tb[t][2], gy2 = sh.tb[t][3];
                float td[4] = { __fdividef((gx1 + gx2) * 0.5f - cx, aw),
                                __fdividef((gy1 + gy2) * 0.5f - cy, aw),
                                __logf(__fdividef(gx2 - gx1, aw)),
                                __logf(__fdividef(gy2 - gy1, aw)) };
                #pragma unroll
                for (int j = 0; j < 4; j++) {
                    float d = fabsf(pb[(cs + j) * FSQ] - td[j]);
                    acc[2] += (d < 1.f) ? 0.5f * d * d : d - 0.5f;
                }
            }
        }
    }
    redN<5>(acc, sh);
    float rPosBce = sh.out[0], rCe = sh.out[1], rSl = sh.out[2];
    int np = (int)sh.out[3], nn = (int)sh.out[4];
    int k = min(3 * np, nn);

    // ---------- Phase 4: hard-negative mining ----------
    float negTop = 0.f;
    if (k > 0) {
        selectBucket<1024>(hist, k, sh);             // level 0: bits 30..21
        int Bq = sh.selBucket;
        int kAbove0 = (int)sh.selAbove;
        int kRem = k - kAbove0;

        if (tid == 0) sh.overflow = 0;
        for (int i = tid; i < 2048; i += BLOCK) hist[i] = 0;
        __syncthreads();

        // vectorized PADDED pass (uint4): sumAbove + per-warp compaction +
        // level-1 hist. Warp collectives need all lanes -> pad + predicate.
        constexpr int A4 = A / 4;                    // A always divisible by 4
        constexpr int A4PAD = ((A4 + BLOCK - 1) / BLOCK) * BLOCK;
        float sa[1] = {0.f};
        unsigned cnt = 0;
        float* seg = list + wid * SEG;
        for (int i = tid; i < A4PAD; i += BLOCK) {
            bool act = i < A4;
            float4 v4 = act ? ((const float4*)s_bce)[i] : make_float4(1.f, 1.f, 1.f, 1.f);
            float mem[4]; unsigned nm = 0;
            float vv[4] = { v4.x, v4.y, v4.z, v4.w };
            #pragma unroll
            for (int j = 0; j < 4; j++) {
                float v = vv[j];
                if (v < 0.f) {
                    float bce = -v;
                    unsigned u = __float_as_uint(bce);
                    int bk = (int)(u >> 21);
                    if (bk > Bq) sa[0] += bce;
                    else if (bk == Bq) {
                        mem[nm++] = bce;
                        atomicAdd(&hist[(u >> 10) & 0x7ff], 1u);  // mantissa bits: spread
                    }
                }
            }
            // warp exclusive scan of per-thread member counts
            unsigned xs = nm;
            #pragma unroll
            for (int off = 1; off < 32; off <<= 1) {
                unsigned y = __shfl_up_sync(0xffffffffu, xs, off);
                if (lane >= off) xs += y;
            }
            unsigned excl = xs - nm;
            unsigned wtot = __shfl_sync(0xffffffffu, xs, 31);
            #pragma unroll
            for (unsigned j = 0; j < 4; j++) {
                if (j < nm) {
                    unsigned pos = cnt + excl + j;
                    if (pos < SEG) seg[pos] = mem[j];
                }
            }
            cnt += wtot;
        }
        if (lane == 0) {
            sh.wcnt[wid] = cnt;
            if (cnt > SEG) sh.overflow = 1;
        }
        redN<1>(sa, sh);                             // syncs; publishes wcnt/overflow
        float sumAbove = sh.out[0];
        int ovf = sh.overflow;                       // block-uniform after sync

        selectBucket<2048>(hist, kRem, sh);          // level 1: bits 20..10
        int B2q = sh.selBucket;
        int kRem2 = kRem - (int)sh.selAbove;

        for (int i = tid; i < 1024; i += BLOCK) hist[i] = 0;
        __syncthreads();

        if (!ovf) {
            // level-2 hist + threshold passes over flat segment list
            for (int s = tid; s < NWARP * SEG; s += BLOCK) {
                if ((unsigned)(s & (SEG - 1)) < sh.wcnt[s / SEG]) {
                    unsigned u = __float_as_uint(list[s]);
                    if (((u >> 10) & 0x7ff) == (unsigned)B2q) atomicAdd(&hist[u & 0x3ff], 1u);
                }
            }
            __syncthreads();
            selectBucket<1024>(hist, kRem2, sh);     // level 2: bits 9..0
            unsigned thr_u = ((unsigned)Bq << 21) | ((unsigned)B2q << 10) | (unsigned)sh.selBucket;
            float thr = __uint_as_float(thr_u);
            float sc[2] = {0.f, 0.f};
            for (int s = tid; s < NWARP * SEG; s += BLOCK) {
                if ((unsigned)(s & (SEG - 1)) < sh.wcnt[s / SEG]) {
                    float v = list[s];
                    if (__float_as_uint(v) > thr_u) { sc[0] += v; sc[1] += 1.f; }
                }
            }
            redN<2>(sc, sh);
            negTop = sumAbove + sh.out[0] + (float)(k - kAbove0 - (int)sh.out[1]) * thr;
        } else {
            // fallback: full-A level-2 + threshold passes (exact, R10 path)
            for (int a = tid; a < A; a += BLOCK) {
                float v = s_bce[a];
                if (v < 0.f) {
                    unsigned u = __float_as_uint(-v);
                    if ((int)(u >> 21) == Bq && (int)((u >> 10) & 0x7ff) == B2q)
                        atomicAdd(&hist[u & 0x3ff], 1u);
                }
            }
            __syncthreads();
            selectBucket<1024>(hist, kRem2, sh);
            unsigned thr_u = ((unsigned)Bq << 21) | ((unsigned)B2q << 10) | (unsigned)sh.selBucket;
            float thr = __uint_as_float(thr_u);
            float sc[2] = {0.f, 0.f};
            for (int a = tid; a < A; a += BLOCK) {
                float v = s_bce[a];
                if (v < 0.f) {
                    unsigned u = __float_as_uint(-v);
                    if (u > thr_u) { sc[0] += -v; sc[1] += 1.f; }
                }
            }
            redN<2>(sc, sh);
            negTop = sh.out[0] + (float)(k - (int)sh.out[1]) * thr;
        }
    }

    // ---------- Phase 5: partials + fused last-block finalize ----------
    if (tid == 0) {
        float ol = (rPosBce + negTop) / (float)max(np + k, 1);
        float cl = rCe / (float)max(np, 1);
        float ll = rSl / (float)max(4 * np, 1);
        float* o = &g_partials[(scale * BATCH + b) * 3];
        o[0] = ol; o[1] = cl; o[2] = ll;
        __threadfence();
        unsigned r = atomicAdd(&g_done, 1);
        sh.isLast = (r == NBLK - 1) ? 1 : 0;
    }
    __syncthreads();
    if (sh.isLast) {
        float v[3] = {0.f, 0.f, 0.f};
        for (int i = tid; i < NBLK; i += BLOCK) {
            v[0] += g_partials[i * 3 + 0];
            v[1] += g_partials[i * 3 + 1];
            v[2] += g_partials[i * 3 + 2];
        }
        redN<3>(v, sh);
        if (tid == 0) {
            float obj = sh.out[0] / (float)BATCH;
            float cls = sh.out[1] / (float)BATCH;
            float loc = sh.out[2] / (float)BATCH;
            out[0] = obj; out[1] = cls; out[2] = loc;
            out[3] = obj + cls + 2.0f * loc;
            g_done = 0;  // reset for next graph replay
        }
    }
}

__global__ __launch_bounds__(BLOCK)
void loss_kernel(const float* __restrict__ pred1, const float* __restrict__ pred2,
                 const float* __restrict__ pred3,
                 const float* __restrict__ tb, const int* __restrict__ tl,
                 float* __restrict__ out)
{
    extern __shared__ unsigned char dyn[];
    __shared__ Sh sh;
    int b = blockIdx.x, scale = blockIdx.y;
    if (scale == 0)      run_scale<56>(pred1, tb, tl, out, b, 0, dyn, sh);
    else if (scale == 1) run_scale<28>(pred2, tb, tl, out, b, 1, dyn, sh);
    else                 run_scale<14>(pred3, tb, tl, out, b, 2, dyn, sh);
}

extern "C" void kernel_launch(void* const* d_in, const int* in_sizes, int n_in,
                              void* d_out, int out_size)
{
    const float* pred1 = (const float*)d_in[0];
    const float* pred2 = (const float*)d_in[1];
    const float* pred3 = (const float*)d_in[2];
    const float* tb    = (const float*)d_in[6];
    const int*   tl    = (const int*)d_in[7];

    cudaFuncSetAttribute(loss_kernel, cudaFuncAttributeMaxDynamicSharedMemorySize,
                         SMEM_BYTES);

    dim3 grid(BATCH, 3);
    loss_kernel<<<grid, BLOCK, SMEM_BYTES>>>(pred1, pred2, pred3, tb, tl, (float*)d_out);
}

// round 14
// speedup vs baseline: 1.5548x; 1.5548x over previous
#include <cuda_runtime.h>
#include <math.h>

#define TGT 20
#define BATCH 64
#define BLOCK 1024
#define NWARP (BLOCK / 32)
#define MAXA 9408
#define NBLK (3 * BATCH)
#define SEG 128                       // per-warp compaction segment (power of 2)

// dynamic smem layout (bytes)
#define OFF_VAL  0            // u32/f32[MAXA] 37632: iou bits -> bce (neg sign-enc)
#define OFF_HIST 37632        // u32[2048]  8192
#define OFF_LIST 45824        // f32[NWARP*SEG] 16384
#define SMEM_BYTES 62208

#define MARK 0x7F800001u      // forced-override marker base (NaN space)
#define IOU03 0x3E99999Au     // bits of 0.3f
#define IOU05 0x3F000000u     // bits of 0.5f

struct Sh {
    float tb[TGT][4];
    float tarea[TGT];
    int   tlab[TGT];
    int   rc0[TGT], rr0[TGT], rw[TGT];
    int   cum[TGT + 1];
    unsigned long long best[TGT];
    float wred[NWARP][8];
    float out[8];
    unsigned warpTot[NWARP];
    unsigned warpSE[NWARP];
    unsigned wcnt[NWARP];
    int selBucket;
    unsigned selAbove;
    int overflow;
    int isLast;
};

__device__ float g_partials[NBLK * 3];
__device__ unsigned g_done = 0;

template<int N>
__device__ __forceinline__ void redN(float* v, Sh& sh) {
    int lane = threadIdx.x & 31, wid = threadIdx.x >> 5;
    #pragma unroll
    for (int i = 0; i < N; i++) {
        float x = v[i];
        #pragma unroll
        for (int off = 16; off; off >>= 1) x += __shfl_xor_sync(0xffffffffu, x, off);
        if (lane == 0) sh.wred[wid][i] = x;
    }
    __syncthreads();
    if (threadIdx.x < N) {
        float s = 0.f;
        #pragma unroll
        for (int w = 0; w < NWARP; w++) s += sh.wred[w][threadIdx.x];
        sh.out[threadIdx.x] = s;
    }
    __syncthreads();
}

template<int NB>
__device__ void selectBucket(unsigned* hist, int kRem, Sh& sh) {
    const int tid = threadIdx.x;
    constexpr int CH = (NB >= BLOCK) ? NB / BLOCK : 1;
    int basei = tid * CH;
    unsigned ls = 0;
    if (basei < NB)
        #pragma unroll
        for (int j = 0; j < CH; j++) ls += hist[basei + j];
    int lane = tid & 31, wid = tid >> 5;
    unsigned v = ls;
    #pragma unroll
    for (int off = 1; off < 32; off <<= 1) {
        unsigned w2 = __shfl_down_sync(0xffffffffu, v, off);
        if (lane + off < 32) v += w2;
    }
    if (lane == 0) sh.warpTot[wid] = v;
    __syncthreads();
    if (tid < NWARP) {
        unsigned wv = sh.warpTot[tid];
        unsigned ws = wv;
        #pragma unroll
        for (int off = 1; off < NWARP; off <<= 1) {
            unsigned w2 = __shfl_down_sync(0xffffffffu, ws, off);
            if (tid + off < NWARP) ws += w2;
        }
        sh.warpSE[tid] = ws - wv;
    }
    __syncthreads();
    unsigned SE = sh.warpSE[wid] + (v - ls);
    if (basei < NB && SE < (unsigned)kRem && SE + ls >= (unsigned)kRem) {
        unsigned c = SE;
        #pragma unroll
        for (int j = CH - 1; j >= 0; j--) {
            unsigned hv = hist[basei + j];
            if (c + hv >= (unsigned)kRem) { sh.selBucket = basei + j; sh.selAbove = c; break; }
            c += hv;
        }
    }
    __syncthreads();
}

template<int F>
__device__ void run_scale(const float* __restrict__ pred,
                          const float* __restrict__ tb,
                          const int* __restrict__ tl,
                          float* __restrict__ out,
                          int b, int scale,
                          unsigned char* dyn, Sh& sh)
{
    constexpr int FSQ = F * F;
    constexpr int A = FSQ * 3;
    constexpr float STRIDE = 448.0f / (float)F;
    constexpr float INV = (float)F / 448.0f;   // exact (1/8, 1/16, 1/32)

    unsigned* s_iou = (unsigned*)(dyn + OFF_VAL);
    float* s_bce = (float*)(dyn + OFF_VAL);      // aliased: iou consumed -> bce stored
    unsigned* hist = (unsigned*)(dyn + OFF_HIST);
    float* list = (float*)(dyn + OFF_LIST);

    const int tid = threadIdx.x;
    const int lane = tid & 31;
    const int wid = tid >> 5;

    if (tid < TGT) {
        const float* p = tb + (size_t)(b * TGT + tid) * 4;
        float x1 = p[0], y1 = p[1], x2 = p[2], y2 = p[3];
        sh.tb[tid][0] = x1; sh.tb[tid][1] = y1; sh.tb[tid][2] = x2; sh.tb[tid][3] = y2;
        sh.tarea[tid] = (x2 - x1) * (y2 - y1);
        sh.tlab[tid] = tl[b * TGT + tid];
        sh.best[tid] = 0ull;
        const float half3 = 1.5f * STRIDE;
        int c0 = max(0, (int)floorf((x1 - half3) * INV - 0.5f));
        int c1 = min(F - 1, (int)ceilf((x2 + half3) * INV - 0.5f));
        int r0 = max(0, (int)floorf((y1 - half3) * INV - 0.5f));
        int r1 = min(F - 1, (int)ceilf((y2 + half3) * INV - 0.5f));
        int w = c1 - c0 + 1, hh = r1 - r0 + 1;
        sh.rc0[tid] = c0; sh.rr0[tid] = r0;
        sh.rw[tid] = max(w, 1);
        sh.cum[tid] = (w > 0 && hh > 0) ? w * hh : 0;  // temp: size
    }
    {
        uint4 z4 = make_uint4(0u, 0u, 0u, 0u);
        uint4* p4 = (uint4*)s_iou;
        for (int i = tid; i < A / 4; i += BLOCK) p4[i] = z4;
    }
    for (int i = tid; i < 1024; i += BLOCK) hist[i] = 0;
    __syncthreads();
    if (tid == 0) {
        int s = 0;
        #pragma unroll
        for (int t = 0; t < TGT; t++) { int sz = sh.cum[t]; sh.cum[t] = s; s += sz; }
        sh.cum[TGT] = s;
    }
    __syncthreads();

    const float* predb = pred + (size_t)b * 24 * FSQ;

    // ---------- Phase 1: flattened (target,cell) scatter ----------
    {
        const int total = sh.cum[TGT];
        const int totalP = (total + BLOCK - 1) & ~(BLOCK - 1);
        int tcur = 0;
        for (int idx = tid; idx < totalP; idx += BLOCK) {
            bool valid = idx < total;
            int tt = -1;
            unsigned long long pk = 0ull;
            if (valid) {
                while (idx >= sh.cum[tcur + 1]) tcur++;
                tt = tcur;
                int local = idx - sh.cum[tt];
                int w = sh.rw[tt];
                int rr = local / w, cc = local - rr * w;
                int r = sh.rr0[tt] + rr, c = sh.rc0[tt] + cc;
                float cx = ((float)c + 0.5f) * STRIDE;
                float cy = ((float)r + 0.5f) * STRIDE;
                float tx1 = sh.tb[tt][0], ty1 = sh.tb[tt][1];
                float tx2 = sh.tb[tt][2], ty2 = sh.tb[tt][3];
                float ta = sh.tarea[tt];
                int abase = (r * F + c) * 3;
                // largest anchor (ai=2) first: concentric squares -> empty
                // ai=2 intersection implies empty ai=0/1.
                const float h2 = 1.5f * STRIDE;
                float iw2 = fminf(cx + h2, tx2) - fmaxf(cx - h2, tx1);
                float ih2 = fminf(cy + h2, ty2) - fmaxf(cy - h2, ty1);
                if (iw2 > 0.f && ih2 > 0.f) {
                    {   // ai = 2
                        float I = iw2 * ih2;
                        float U = (2.f * h2) * (2.f * h2) + ta - I;
                        unsigned ib = __float_as_uint(__fdividef(I, U + 1e-9f));
                        if (ib >= IOU03) atomicMax(&s_iou[abase + 2], ib);
                        unsigned long long cand = ((unsigned long long)ib << 32) |
                            (unsigned long long)(0xffffffffu - (unsigned)(abase + 2));
                        if (cand > pk) pk = cand;
                    }
                    #pragma unroll
                    for (int ai = 0; ai < 2; ai++) {
                        float half = (1.0f + 0.25f * (float)ai) * STRIDE;
                        float iw = fminf(cx + half, tx2) - fmaxf(cx - half, tx1);
                        float ih = fminf(cy + half, ty2) - fmaxf(cy - half, ty1);
                        if (iw > 0.f && ih > 0.f) {
                            float I = iw * ih;
                            float areaA = (2.f * half) * (2.f * half);
                            float U = areaA + ta - I;
                            unsigned ib = __float_as_uint(__fdividef(I, U + 1e-9f));
                            if (ib >= IOU03) atomicMax(&s_iou[abase + ai], ib);
                            unsigned long long cand = ((unsigned long long)ib << 32) |
                                (unsigned long long)(0xffffffffu - (unsigned)(abase + ai));
                            if (cand > pk) pk = cand;
                        }
                    }
                }
            }
            #pragma unroll
            for (int off = 1; off < 32; off <<= 1) {
                unsigned long long opk = __shfl_up_sync(0xffffffffu, pk, off);
                int ot = __shfl_up_sync(0xffffffffu, tt, off);
                if (lane >= off && ot == tt && opk > pk) pk = opk;
            }
            unsigned mask = __match_any_sync(0xffffffffu, tt);
            int hi = 31 - __clz(mask);
            if (tt >= 0 && lane == hi && pk)
                atomicMax(&sh.best[tt], pk);
        }
    }
    __syncthreads();

    // ---------- Phase 2: forced-positive override marker (last target wins) ----------
    if (tid == 0) {
        #pragma unroll
        for (int t = 0; t < TGT; t++) {
            if (sh.best[t]) {
                unsigned a = 0xffffffffu - (unsigned)(sh.best[t] & 0xffffffffull);
                s_iou[a] = MARK + (unsigned)t;
            }
        }
    }
    __syncthreads();

    // ---------- Phase 3: BCE + fused level-0 hist + positive losses ----------
    float acc[5] = {0.f, 0.f, 0.f, 0.f, 0.f}; // posBce, ce, sl, cntPos, cntNeg
    constexpr int FSQP = ((FSQ + BLOCK - 1) / BLOCK) * BLOCK;
    for (int cell = tid; cell < FSQP; cell += BLOCK) {
        bool act = cell < FSQ;
        int row = 0, col = 0;
        float cx = 0.f, cy = 0.f;
        if (act) {
            row = cell / F; col = cell - row * F;
            cx = ((float)col + 0.5f) * STRIDE;
            cy = ((float)row + 0.5f) * STRIDE;
        }
        #pragma unroll
        for (int ai = 0; ai < 3; ai++) {
            int a = cell * 3 + ai;
            unsigned ib = 0; float x = 0.f;
            if (act) { ib = s_iou[a]; x = predb[(ai * 8 + 4) * FSQ + cell]; }
            bool forced = ib >= MARK;
            bool pos = forced || (act && ib >= IOU05);
            bool neg = act && !forced && ib < IOU03;
            float bce = fmaxf(x, 0.f) - (pos ? x : 0.f) + __logf(1.f + __expf(-fabsf(x)));
            if (act) s_bce[a] = neg ? -bce : bce;
            int bin = neg ? (int)(__float_as_uint(bce) >> 21) : -1;
            unsigned mask = __match_any_sync(0xffffffffu, bin);
            if (bin >= 0) {
                acc[4] += 1.f;
                if (lane == __ffs(mask) - 1) atomicAdd(&hist[bin], (unsigned)__popc(mask));
            }
            if (pos) {
                acc[3] += 1.f; acc[0] += bce;
                int t = 0;
                if (forced) t = (int)(ib - MARK);
                else {
                    #pragma unroll
                    for (int q = 0; q < TGT; q++) {
                        float half = (1.0f + 0.25f * (float)ai) * STRIDE;
                        float lx = fmaxf(cx - half, sh.tb[q][0]);
                        float ly = fmaxf(cy - half, sh.tb[q][1]);
                        float rx = fminf(cx + half, sh.tb[q][2]);
                        float ry = fminf(cy + half, sh.tb[q][3]);
                        float iw = rx - lx, ih = ry - ly;
                        if (iw > 0.f && ih > 0.f) {
                            float I = iw * ih;
                            float areaA = (2.f * half) * (2.f * half);
                            float U = areaA + sh.tarea[q] - I;
                            if (__float_as_uint(__fdividef(I, U + 1e-9f)) == ib) { t = q; break; }
                        }
                    }
                }
                const float* pb = predb + cell;
                int cs = ai * 8;
                float c0v = pb[(cs + 5) * FSQ], c1v = pb[(cs + 6) * FSQ], c2v = pb[(cs + 7) * FSQ];
                float m = fmaxf(c0v, fmaxf(c1v, c2v));
                float lse = m + __logf(__expf(c0v - m) + __expf(c1v - m) + __expf(c2v - m));
                int tg = sh.tlab[t] - 1;
                float ct = (tg == 0) ? c0v : ((tg == 1) ? c1v : c2v);
                acc[1] += lse - ct;
                float half = (1.0f + 0.25f * (float)ai) * STRIDE;
                float aw = 2.f * half;
                float gx1 = sh.tb[t][0], gy1 = sh.tb[t][1];
                float gx2 = sh.tb[t][2], gy2 = sh.tb[t][3];
                float td[4] = { __fdividef((gx1 + gx2) * 0.5f - cx, aw),
                                __fdividef((gy1 + gy2) * 0.5f - cy, aw),
                                __logf(__fdividef(gx2 - gx1, aw)),
                                __logf(__fdividef(gy2 - gy1, aw)) };
                #pragma unroll
                for (int j = 0; j < 4; j++) {
                    float d = fabsf(pb[(cs + j) * FSQ] - td[j]);
                    acc[2] += (d < 1.f) ? 0.5f * d * d : d - 0.5f;
                }
            }
        }
    }
    redN<5>(acc, sh);
    float rPosBce = sh.out[0], rCe = sh.out[1], rSl = sh.out[2];
    int np = (int)sh.out[3], nn = (int)sh.out[4];
    int k = min(3 * np, nn);

    // ---------- Phase 4: hard-negative mining (R12 scalar compaction) ----------
    float negTop = 0.f;
    if (k > 0) {
        selectBucket<1024>(hist, k, sh);             // level 0: bits 30..21
        int Bq = sh.selBucket;
        int kAbove0 = (int)sh.selAbove;
        int kRem = k - kAbove0;

        if (tid == 0) sh.overflow = 0;
        for (int i = tid; i < 2048; i += BLOCK) hist[i] = 0;
        __syncthreads();

        // single PADDED full-A pass: sumAbove + per-warp segment compaction
        // + level-1 hist. Loop padded to BLOCK multiple: warp collectives
        // below require all lanes present (A=2352/588 are NOT warp multiples).
        constexpr int APAD = ((A + BLOCK - 1) / BLOCK) * BLOCK;
        float sa[1] = {0.f};
        unsigned cnt = 0;
        float* seg = list + wid * SEG;
        for (int a = tid; a < APAD; a += BLOCK) {
            bool act = a < A;
            float v = act ? s_bce[a] : 1.0f;         // positive -> not neg
            bool isneg = v < 0.f;
            float bce = -v;
            unsigned u = __float_as_uint(bce);
            int bk = isneg ? (int)(u >> 21) : -1;
            if (bk > Bq) sa[0] += bce;
            bool inB = (bk == Bq);
            unsigned bal = __ballot_sync(0xffffffffu, inB);
            if (inB) {
                unsigned pos = cnt + (unsigned)__popc(bal & ((1u << lane) - 1u));
                if (pos < SEG) seg[pos] = bce;
            }
            cnt += (unsigned)__popc(bal);
            int b1 = inB ? (int)((u >> 10) & 0x7ff) : -1;
            unsigned mm = __match_any_sync(0xffffffffu, b1);
            if (b1 >= 0 && lane == __ffs(mm) - 1)
                atomicAdd(&hist[b1], (unsigned)__popc(mm));
        }
        if (lane == 0) {
            sh.wcnt[wid] = cnt;
            if (cnt > SEG) sh.overflow = 1;
        }
        redN<1>(sa, sh);                             // syncs; publishes wcnt/overflow
        float sumAbove = sh.out[0];
        int ovf = sh.overflow;                       // block-uniform after sync

        selectBucket<2048>(hist, kRem, sh);          // level 1: bits 20..10
        int B2q = sh.selBucket;
        int kRem2 = kRem - (int)sh.selAbove;

        for (int i = tid; i < 1024; i += BLOCK) hist[i] = 0;
        __syncthreads();

        if (!ovf) {
            // level-2 hist + threshold passes over flat segment list
            for (int s = tid; s < NWARP * SEG; s += BLOCK) {
                if ((unsigned)(s & (SEG - 1)) < sh.wcnt[s / SEG]) {
                    unsigned u = __float_as_uint(list[s]);
                    if (((u >> 10) & 0x7ff) == (unsigned)B2q) atomicAdd(&hist[u & 0x3ff], 1u);
                }
            }
            __syncthreads();
            selectBucket<1024>(hist, kRem2, sh);     // level 2: bits 9..0
            unsigned thr_u = ((unsigned)Bq << 21) | ((unsigned)B2q << 10) | (unsigned)sh.selBucket;
            float thr = __uint_as_float(thr_u);
            float sc[2] = {0.f, 0.f};
            for (int s = tid; s < NWARP * SEG; s += BLOCK) {
                if ((unsigned)(s & (SEG - 1)) < sh.wcnt[s / SEG]) {
                    float v = list[s];
                    if (__float_as_uint(v) > thr_u) { sc[0] += v; sc[1] += 1.f; }
                }
            }
            redN<2>(sc, sh);
            negTop = sumAbove + sh.out[0] + (float)(k - kAbove0 - (int)sh.out[1]) * thr;
        } else {
            // fallback: full-A level-2 + threshold passes (exact, R10 path)
            for (int a = tid; a < A; a += BLOCK) {
                float v = s_bce[a];
                if (v < 0.f) {
                    unsigned u = __float_as_uint(-v);
                    if ((int)(u >> 21) == Bq && (int)((u >> 10) & 0x7ff) == B2q)
                        atomicAdd(&hist[u & 0x3ff], 1u);
                }
            }
            __syncthreads();
            selectBucket<1024>(hist, kRem2, sh);
            unsigned thr_u = ((unsigned)Bq << 21) | ((unsigned)B2q << 10) | (unsigned)sh.selBucket;
            float thr = __uint_as_float(thr_u);
            float sc[2] = {0.f, 0.f};
            for (int a = tid; a < A; a += BLOCK) {
                float v = s_bce[a];
                if (v < 0.f) {
                    unsigned u = __float_as_uint(-v);
                    if (u > thr_u) { sc[0] += -v; sc[1] += 1.f; }
                }
            }
            redN<2>(sc, sh);
            negTop = sh.out[0] + (float)(k - (int)sh.out[1]) * thr;
        }
    }

    // ---------- Phase 5: partials + fused last-block finalize ----------
    if (tid == 0) {
        float ol = (rPosBce + negTop) / (float)max(np + k, 1);
        float cl = rCe / (float)max(np, 1);
        float ll = rSl / (float)max(4 * np, 1);
        float* o = &g_partials[(scale * BATCH + b) * 3];
        o[0] = ol; o[1] = cl; o[2] = ll;
        __threadfence();
        unsigned r = atomicAdd(&g_done, 1);
        sh.isLast = (r == NBLK - 1) ? 1 : 0;
    }
    __syncthreads();
    if (sh.isLast) {
        float v[3] = {0.f, 0.f, 0.f};
        for (int i = tid; i < NBLK; i += BLOCK) {
            v[0] += g_partials[i * 3 + 0];
            v[1] += g_partials[i * 3 + 1];
            v[2] += g_partials[i * 3 + 2];
        }
        redN<3>(v, sh);
        if (tid == 0) {
            float obj = sh.out[0] / (float)BATCH;
            float cls = sh.out[1] / (float)BATCH;
            float loc = sh.out[2] / (float)BATCH;
            out[0] = obj; out[1] = cls; out[2] = loc;
            out[3] = obj + cls + 2.0f * loc;
            g_done = 0;  // reset for next graph replay
        }
    }
}

__global__ __launch_bounds__(BLOCK)
void loss_kernel(const float* __restrict__ pred1, const float* __restrict__ pred2,
                 const float* __restrict__ pred3,
                 const float* __restrict__ tb, const int* __restrict__ tl,
                 float* __restrict__ out)
{
    extern __shared__ unsigned char dyn[];
    __shared__ Sh sh;
    int b = blockIdx.x, scale = blockIdx.y;
    if (scale == 0)      run_scale<56>(pred1, tb, tl, out, b, 0, dyn, sh);
    else if (scale == 1) run_scale<28>(pred2, tb, tl, out, b, 1, dyn, sh);
    else                 run_scale<14>(pred3, tb, tl, out, b, 2, dyn, sh);
}

extern "C" void kernel_launch(void* const* d_in, const int* in_sizes, int n_in,
                              void* d_out, int out_size)
{
    const float* pred1 = (const float*)d_in[0];
    const float* pred2 = (const float*)d_in[1];
    const float* pred3 = (const float*)d_in[2];
    const float* tb    = (const float*)d_in[6];
    const int*   tl    = (const int*)d_in[7];

    cudaFuncSetAttribute(loss_kernel, cudaFuncAttributeMaxDynamicSharedMemorySize,
                         SMEM_BYTES);

    dim3 grid(BATCH, 3);
    loss_kernel<<<grid, BLOCK, SMEM_BYTES>>>(pred1, pred2, pred3, tb, tl, (float*)d_out);
}

// round 15
// speedup vs baseline: 1.5561x; 1.0009x over previous
#include <cuda_runtime.h>
#include <math.h>

#define TGT 20
#define BATCH 64
#define BLOCK 1024
#define NWARP (BLOCK / 32)
#define MAXA 9408
#define NBLK (3 * BATCH)
#define SEG 128                       // per-warp compaction segment (power of 2)

// dynamic smem layout (bytes)
#define OFF_VAL  0            // u32/f32[MAXA] 37632: iou bits -> bce (neg sign-enc)
#define OFF_OBJ  37632        // f32[MAXA] 37632: prefetched obj logits [ai][cell]
#define OFF_HIST 75264        // u32[2048]  8192
#define OFF_LIST 83456        // f32[NWARP*SEG] 16384
#define SMEM_BYTES 99840

#define MARK 0x7F800001u      // forced-override marker base (NaN space)
#define IOU03 0x3E99999Au     // bits of 0.3f
#define IOU05 0x3F000000u     // bits of 0.5f

struct Sh {
    float tb[TGT][4];
    float tarea[TGT];
    int   tlab[TGT];
    int   rc0[TGT], rr0[TGT], rw[TGT];
    int   cum[TGT + 1];
    unsigned long long best[TGT];
    float wred[NWARP][8];
    float out[8];
    unsigned warpTot[NWARP];
    unsigned warpSE[NWARP];
    unsigned wcnt[NWARP];
    int selBucket;
    unsigned selAbove;
    int overflow;
    int isLast;
};

__device__ float g_partials[NBLK * 3];
__device__ unsigned g_done = 0;

template<int N>
__device__ __forceinline__ void redN(float* v, Sh& sh) {
    int lane = threadIdx.x & 31, wid = threadIdx.x >> 5;
    #pragma unroll
    for (int i = 0; i < N; i++) {
        float x = v[i];
        #pragma unroll
        for (int off = 16; off; off >>= 1) x += __shfl_xor_sync(0xffffffffu, x, off);
        if (lane == 0) sh.wred[wid][i] = x;
    }
    __syncthreads();
    if (threadIdx.x < N) {
        float s = 0.f;
        #pragma unroll
        for (int w = 0; w < NWARP; w++) s += sh.wred[w][threadIdx.x];
        sh.out[threadIdx.x] = s;
    }
    __syncthreads();
}

template<int NB>
__device__ void selectBucket(unsigned* hist, int kRem, Sh& sh) {
    const int tid = threadIdx.x;
    constexpr int CH = (NB >= BLOCK) ? NB / BLOCK : 1;
    int basei = tid * CH;
    unsigned ls = 0;
    if (basei < NB)
        #pragma unroll
        for (int j = 0; j < CH; j++) ls += hist[basei + j];
    int lane = tid & 31, wid = tid >> 5;
    unsigned v = ls;
    #pragma unroll
    for (int off = 1; off < 32; off <<= 1) {
        unsigned w2 = __shfl_down_sync(0xffffffffu, v, off);
        if (lane + off < 32) v += w2;
    }
    if (lane == 0) sh.warpTot[wid] = v;
    __syncthreads();
    if (tid < NWARP) {
        unsigned wv = sh.warpTot[tid];
        unsigned ws = wv;
        #pragma unroll
        for (int off = 1; off < NWARP; off <<= 1) {
            unsigned w2 = __shfl_down_sync(0xffffffffu, ws, off);
            if (tid + off < NWARP) ws += w2;
        }
        sh.warpSE[tid] = ws - wv;
    }
    __syncthreads();
    unsigned SE = sh.warpSE[wid] + (v - ls);
    if (basei < NB && SE < (unsigned)kRem && SE + ls >= (unsigned)kRem) {
        unsigned c = SE;
        #pragma unroll
        for (int j = CH - 1; j >= 0; j--) {
            unsigned hv = hist[basei + j];
            if (c + hv >= (unsigned)kRem) { sh.selBucket = basei + j; sh.selAbove = c; break; }
            c += hv;
        }
    }
    __syncthreads();
}

template<int F>
__device__ void run_scale(const float* __restrict__ pred,
                          const float* __restrict__ tb,
                          const int* __restrict__ tl,
                          float* __restrict__ out,
                          int b, int scale,
                          unsigned char* dyn, Sh& sh)
{
    constexpr int FSQ = F * F;
    constexpr int A = FSQ * 3;
    constexpr float STRIDE = 448.0f / (float)F;
    constexpr float INV = (float)F / 448.0f;   // exact (1/8, 1/16, 1/32)

    unsigned* s_iou = (unsigned*)(dyn + OFF_VAL);
    float* s_bce = (float*)(dyn + OFF_VAL);      // aliased: iou consumed -> bce stored
    float* s_obj = (float*)(dyn + OFF_OBJ);      // prefetched obj logits [ai][cell]
    unsigned* hist = (unsigned*)(dyn + OFF_HIST);
    float* list = (float*)(dyn + OFF_LIST);

    const int tid = threadIdx.x;
    const int lane = tid & 31;
    const int wid = tid >> 5;

    const float* predb = pred + (size_t)b * 24 * FSQ;

    // prefetch obj planes FIRST: LDG latency overlaps setup + phase 1;
    // ordered before phase-3 reads by the intervening __syncthreads.
    #pragma unroll
    for (int ai = 0; ai < 3; ai++) {
        const float4* src = (const float4*)(predb + (ai * 8 + 4) * FSQ);
        float4* dst = (float4*)(s_obj + ai * FSQ);
        for (int i = tid; i < FSQ / 4; i += BLOCK) dst[i] = src[i];
    }

    if (tid < TGT) {
        const float* p = tb + (size_t)(b * TGT + tid) * 4;
        float x1 = p[0], y1 = p[1], x2 = p[2], y2 = p[3];
        sh.tb[tid][0] = x1; sh.tb[tid][1] = y1; sh.tb[tid][2] = x2; sh.tb[tid][3] = y2;
        sh.tarea[tid] = (x2 - x1) * (y2 - y1);
        sh.tlab[tid] = tl[b * TGT + tid];
        sh.best[tid] = 0ull;
        const float half3 = 1.5f * STRIDE;
        int c0 = max(0, (int)floorf((x1 - half3) * INV - 0.5f));
        int c1 = min(F - 1, (int)ceilf((x2 + half3) * INV - 0.5f));
        int r0 = max(0, (int)floorf((y1 - half3) * INV - 0.5f));
        int r1 = min(F - 1, (int)ceilf((y2 + half3) * INV - 0.5f));
        int w = c1 - c0 + 1, hh = r1 - r0 + 1;
        sh.rc0[tid] = c0; sh.rr0[tid] = r0;
        sh.rw[tid] = max(w, 1);
        sh.cum[tid] = (w > 0 && hh > 0) ? w * hh : 0;  // temp: size
    }
    {
        uint4 z4 = make_uint4(0u, 0u, 0u, 0u);
        uint4* p4 = (uint4*)s_iou;
        for (int i = tid; i < A / 4; i += BLOCK) p4[i] = z4;
    }
    for (int i = tid; i < 1024; i += BLOCK) hist[i] = 0;
    __syncthreads();
    if (tid == 0) {
        int s = 0;
        #pragma unroll
        for (int t = 0; t < TGT; t++) { int sz = sh.cum[t]; sh.cum[t] = s; s += sz; }
        sh.cum[TGT] = s;
    }
    __syncthreads();

    // ---------- Phase 1: flattened (target,cell) scatter ----------
    {
        const int total = sh.cum[TGT];
        const int totalP = (total + BLOCK - 1) & ~(BLOCK - 1);
        int tcur = 0;
        for (int idx = tid; idx < totalP; idx += BLOCK) {
            bool valid = idx < total;
            int tt = -1;
            unsigned long long pk = 0ull;
            if (valid) {
                while (idx >= sh.cum[tcur + 1]) tcur++;
                tt = tcur;
                int local = idx - sh.cum[tt];
                int w = sh.rw[tt];
                int rr = local / w, cc = local - rr * w;
                int r = sh.rr0[tt] + rr, c = sh.rc0[tt] + cc;
                float cx = ((float)c + 0.5f) * STRIDE;
                float cy = ((float)r + 0.5f) * STRIDE;
                float tx1 = sh.tb[tt][0], ty1 = sh.tb[tt][1];
                float tx2 = sh.tb[tt][2], ty2 = sh.tb[tt][3];
                float ta = sh.tarea[tt];
                int abase = (r * F + c) * 3;
                // largest anchor (ai=2) first: concentric squares -> empty
                // ai=2 intersection implies empty ai=0/1.
                const float h2 = 1.5f * STRIDE;
                float iw2 = fminf(cx + h2, tx2) - fmaxf(cx - h2, tx1);
                float ih2 = fminf(cy + h2, ty2) - fmaxf(cy - h2, ty1);
                if (iw2 > 0.f && ih2 > 0.f) {
                    {   // ai = 2
                        float I = iw2 * ih2;
                        float U = (2.f * h2) * (2.f * h2) + ta - I;
                        unsigned ib = __float_as_uint(__fdividef(I, U + 1e-9f));
                        if (ib >= IOU03) atomicMax(&s_iou[abase + 2], ib);
                        unsigned long long cand = ((unsigned long long)ib << 32) |
                            (unsigned long long)(0xffffffffu - (unsigned)(abase + 2));
                        if (cand > pk) pk = cand;
                    }
                    #pragma unroll
                    for (int ai = 0; ai < 2; ai++) {
                        float half = (1.0f + 0.25f * (float)ai) * STRIDE;
                        float iw = fminf(cx + half, tx2) - fmaxf(cx - half, tx1);
                        float ih = fminf(cy + half, ty2) - fmaxf(cy - half, ty1);
                        if (iw > 0.f && ih > 0.f) {
                            float I = iw * ih;
                            float areaA = (2.f * half) * (2.f * half);
                            float U = areaA + ta - I;
                            unsigned ib = __float_as_uint(__fdividef(I, U + 1e-9f));
                            if (ib >= IOU03) atomicMax(&s_iou[abase + ai], ib);
                            unsigned long long cand = ((unsigned long long)ib << 32) |
                                (unsigned long long)(0xffffffffu - (unsigned)(abase + ai));
                            if (cand > pk) pk = cand;
                        }
                    }
                }
            }
            #pragma unroll
            for (int off = 1; off < 32; off <<= 1) {
                unsigned long long opk = __shfl_up_sync(0xffffffffu, pk, off);
                int ot = __shfl_up_sync(0xffffffffu, tt, off);
                if (lane >= off && ot == tt && opk > pk) pk = opk;
            }
            unsigned mask = __match_any_sync(0xffffffffu, tt);
            int hi = 31 - __clz(mask);
            if (tt >= 0 && lane == hi && pk)
                atomicMax(&sh.best[tt], pk);
        }
    }
    __syncthreads();

    // ---------- Phase 2: forced-positive override marker (last target wins) ----------
    if (tid == 0) {
        #pragma unroll
        for (int t = 0; t < TGT; t++) {
            if (sh.best[t]) {
                unsigned a = 0xffffffffu - (unsigned)(sh.best[t] & 0xffffffffull);
                s_iou[a] = MARK + (unsigned)t;
            }
        }
    }
    __syncthreads();

    // ---------- Phase 3: BCE + fused level-0 hist + positive losses ----------
    float acc[5] = {0.f, 0.f, 0.f, 0.f, 0.f}; // posBce, ce, sl, cntPos, cntNeg
    constexpr int FSQP = ((FSQ + BLOCK - 1) / BLOCK) * BLOCK;
    for (int cell = tid; cell < FSQP; cell += BLOCK) {
        bool act = cell < FSQ;
        int row = 0, col = 0;
        float cx = 0.f, cy = 0.f;
        if (act) {
            row = cell / F; col = cell - row * F;
            cx = ((float)col + 0.5f) * STRIDE;
            cy = ((float)row + 0.5f) * STRIDE;
        }
        #pragma unroll
        for (int ai = 0; ai < 3; ai++) {
            int a = cell * 3 + ai;
            unsigned ib = 0; float x = 0.f;
            if (act) { ib = s_iou[a]; x = s_obj[ai * FSQ + cell]; }
            bool forced = ib >= MARK;
            bool pos = forced || (act && ib >= IOU05);
            bool neg = act && !forced && ib < IOU03;
            float bce = fmaxf(x, 0.f) - (pos ? x : 0.f) + __logf(1.f + __expf(-fabsf(x)));
            if (act) s_bce[a] = neg ? -bce : bce;
            int bin = neg ? (int)(__float_as_uint(bce) >> 21) : -1;
            unsigned mask = __match_any_sync(0xffffffffu, bin);
            if (bin >= 0) {
                acc[4] += 1.f;
                if (lane == __ffs(mask) - 1) atomicAdd(&hist[bin], (unsigned)__popc(mask));
            }
            if (pos) {
                acc[3] += 1.f; acc[0] += bce;
                int t = 0;
                if (forced) t = (int)(ib - MARK);
                else {
                    #pragma unroll
                    for (int q = 0; q < TGT; q++) {
                        float half = (1.0f + 0.25f * (float)ai) * STRIDE;
                        float lx = fmaxf(cx - half, sh.tb[q][0]);
                        float ly = fmaxf(cy - half, sh.tb[q][1]);
                        float rx = fminf(cx + half, sh.tb[q][2]);
                        float ry = fminf(cy + half, sh.tb[q][3]);
                        float iw = rx - lx, ih = ry - ly;
                        if (iw > 0.f && ih > 0.f) {
                            float I = iw * ih;
                            float areaA = (2.f * half) * (2.f * half);
                            float U = areaA + sh.tarea[q] - I;
                            if (__float_as_uint(__fdividef(I, U + 1e-9f)) == ib) { t = q; break; }
                        }
                    }
                }
                const float* pb = predb + cell;
                int cs = ai * 8;
                float c0v = pb[(cs + 5) * FSQ], c1v = pb[(cs + 6) * FSQ], c2v = pb[(cs + 7) * FSQ];
                float m = fmaxf(c0v, fmaxf(c1v, c2v));
                float lse = m + __logf(__expf(c0v - m) + __expf(c1v - m) + __expf(c2v - m));
                int tg = sh.tlab[t] - 1;
                float ct = (tg == 0) ? c0v : ((tg == 1) ? c1v : c2v);
                acc[1] += lse - ct;
                float half = (1.0f + 0.25f * (float)ai) * STRIDE;
                float aw = 2.f * half;
                float gx1 = sh.tb[t][0], gy1 = sh.tb[t][1];
                float gx2 = sh.tb[t][2], gy2 = sh.tb[t][3];
                float td[4] = { __fdividef((gx1 + gx2) * 0.5f - cx, aw),
                                __fdividef((gy1 + gy2) * 0.5f - cy, aw),
                                __logf(__fdividef(gx2 - gx1, aw)),
                                __logf(__fdividef(gy2 - gy1, aw)) };
                #pragma unroll
                for (int j = 0; j < 4; j++) {
                    float d = fabsf(pb[(cs + j) * FSQ] - td[j]);
                    acc[2] += (d < 1.f) ? 0.5f * d * d : d - 0.5f;
                }
            }
        }
    }
    redN<5>(acc, sh);
    float rPosBce = sh.out[0], rCe = sh.out[1], rSl = sh.out[2];
    int np = (int)sh.out[3], nn = (int)sh.out[4];
    int k = min(3 * np, nn);

    // ---------- Phase 4: hard-negative mining (scalar compaction) ----------
    float negTop = 0.f;
    if (k > 0) {
        selectBucket<1024>(hist, k, sh);             // level 0: bits 30..21
        int Bq = sh.selBucket;
        int kAbove0 = (int)sh.selAbove;
        int kRem = k - kAbove0;

        if (tid == 0) sh.overflow = 0;
        for (int i = tid; i < 2048; i += BLOCK) hist[i] = 0;
        __syncthreads();

        // single PADDED full-A pass: sumAbove + per-warp segment compaction
        // + level-1 hist. Loop padded to BLOCK multiple: warp collectives
        // below require all lanes present (A=2352/588 are NOT warp multiples).
        constexpr int APAD = ((A + BLOCK - 1) / BLOCK) * BLOCK;
        float sa[1] = {0.f};
        unsigned cnt = 0;
        float* seg = list + wid * SEG;
        for (int a = tid; a < APAD; a += BLOCK) {
            bool act = a < A;
            float v = act ? s_bce[a] : 1.0f;         // positive -> not neg
            bool isneg = v < 0.f;
            float bce = -v;
            unsigned u = __float_as_uint(bce);
            int bk = isneg ? (int)(u >> 21) : -1;
            if (bk > Bq) sa[0] += bce;
            bool inB = (bk == Bq);
            unsigned bal = __ballot_sync(0xffffffffu, inB);
            if (inB) {
                unsigned pos = cnt + (unsigned)__popc(bal & ((1u << lane) - 1u));
                if (pos < SEG) seg[pos] = bce;
            }
            cnt += (unsigned)__popc(bal);
            int b1 = inB ? (int)((u >> 10) & 0x7ff) : -1;
            unsigned mm = __match_any_sync(0xffffffffu, b1);
            if (b1 >= 0 && lane == __ffs(mm) - 1)
                atomicAdd(&hist[b1], (unsigned)__popc(mm));
        }
        if (lane == 0) {
            sh.wcnt[wid] = cnt;
            if (cnt > SEG) sh.overflow = 1;
        }
        redN<1>(sa, sh);                             // syncs; publishes wcnt/overflow
        float sumAbove = sh.out[0];
        int ovf = sh.overflow;                       // block-uniform after sync

        selectBucket<2048>(hist, kRem, sh);          // level 1: bits 20..10
        int B2q = sh.selBucket;
        int kRem2 = kRem - (int)sh.selAbove;

        for (int i = tid; i < 1024; i += BLOCK) hist[i] = 0;
        __syncthreads();

        if (!ovf) {
            // level-2 hist + threshold passes over flat segment list
            for (int s = tid; s < NWARP * SEG; s += BLOCK) {
                if ((unsigned)(s & (SEG - 1)) < sh.wcnt[s / SEG]) {
                    unsigned u = __float_as_uint(list[s]);
                    if (((u >> 10) & 0x7ff) == (unsigned)B2q) atomicAdd(&hist[u & 0x3ff], 1u);
                }
            }
            __syncthreads();
            selectBucket<1024>(hist, kRem2, sh);     // level 2: bits 9..0
            unsigned thr_u = ((unsigned)Bq << 21) | ((unsigned)B2q << 10) | (unsigned)sh.selBucket;
            float thr = __uint_as_float(thr_u);
            float sc[2] = {0.f, 0.f};
            for (int s = tid; s < NWARP * SEG; s += BLOCK) {
                if ((unsigned)(s & (SEG - 1)) < sh.wcnt[s / SEG]) {
                    float v = list[s];
                    if (__float_as_uint(v) > thr_u) { sc[0] += v; sc[1] += 1.f; }
                }
            }
            redN<2>(sc, sh);
            negTop = sumAbove + sh.out[0] + (float)(k - kAbove0 - (int)sh.out[1]) * thr;
        } else {
            // fallback: full-A level-2 + threshold passes (exact)
            for (int a = tid; a < A; a += BLOCK) {
                float v = s_bce[a];
                if (v < 0.f) {
                    unsigned u = __float_as_uint(-v);
                    if ((int)(u >> 21) == Bq && (int)((u >> 10) & 0x7ff) == B2q)
                        atomicAdd(&hist[u & 0x3ff], 1u);
                }
            }
            __syncthreads();
            selectBucket<1024>(hist, kRem2, sh);
            unsigned thr_u = ((unsigned)Bq << 21) | ((unsigned)B2q << 10) | (unsigned)sh.selBucket;
            float thr = __uint_as_float(thr_u);
            float sc[2] = {0.f, 0.f};
            for (int a = tid; a < A; a += BLOCK) {
                float v = s_bce[a];
                if (v < 0.f) {
                    unsigned u = __float_as_uint(-v);
                    if (u > thr_u) { sc[0] += -v; sc[1] += 1.f; }
                }
            }
            redN<2>(sc, sh);
            negTop = sh.out[0] + (float)(k - (int)sh.out[1]) * thr;
        }
    }

    // ---------- Phase 5: partials + fused last-block finalize ----------
    if (tid == 0) {
        float ol = (rPosBce + negTop) / (float)max(np + k, 1);
        float cl = rCe / (float)max(np, 1);
        float ll = rSl / (float)max(4 * np, 1);
        float* o = &g_partials[(scale * BATCH + b) * 3];
        o[0] = ol; o[1] = cl; o[2] = ll;
        __threadfence();
        unsigned r = atomicAdd(&g_done, 1);
        sh.isLast = (r == NBLK - 1) ? 1 : 0;
    }
    __syncthreads();
    if (sh.isLast) {
        float v[3] = {0.f, 0.f, 0.f};
        for (int i = tid; i < NBLK; i += BLOCK) {
            v[0] += g_partials[i * 3 + 0];
            v[1] += g_partials[i * 3 + 1];
            v[2] += g_partials[i * 3 + 2];
        }
        redN<3>(v, sh);
        if (tid == 0) {
            float obj = sh.out[0] / (float)BATCH;
            float cls = sh.out[1] / (float)BATCH;
            float loc = sh.out[2] / (float)BATCH;
            out[0] = obj; out[1] = cls; out[2] = loc;
            out[3] = obj + cls + 2.0f * loc;
            g_done = 0;  // reset for next graph replay
        }
    }
}

__global__ __launch_bounds__(BLOCK)
void loss_kernel(const float* __restrict__ pred1, const float* __restrict__ pred2,
                 const float* __restrict__ pred3,
                 const float* __restrict__ tb, const int* __restrict__ tl,
                 float* __restrict__ out)
{
    extern __shared__ unsigned char dyn[];
    __shared__ Sh sh;
    int b = blockIdx.x, scale = blockIdx.y;
    if (scale == 0)      run_scale<56>(pred1, tb, tl, out, b, 0, dyn, sh);
    else if (scale == 1) run_scale<28>(pred2, tb, tl, out, b, 1, dyn, sh);
    else                 run_scale<14>(pred3, tb, tl, out, b, 2, dyn, sh);
}

extern "C" void kernel_launch(void* const* d_in, const int* in_sizes, int n_in,
                              void* d_out, int out_size)
{
    const float* pred1 = (const float*)d_in[0];
    const float* pred2 = (const float*)d_in[1];
    const float* pred3 = (const float*)d_in[2];
    const float* tb    = (const float*)d_in[6];
    const int*   tl    = (const int*)d_in[7];

    cudaFuncSetAttribute(loss_kernel, cudaFuncAttributeMaxDynamicSharedMemorySize,
                         SMEM_BYTES);

    dim3 grid(BATCH, 3);
    loss_kernel<<<grid, BLOCK, SMEM_BYTES>>>(pred1, pred2, pred3, tb, tl, (float*)d_out);
}